// round 1
// baseline (speedup 1.0000x reference)
#include <cuda_runtime.h>

// Problem constants (from reference): x [B=16, T=8192, C=64] fp32,
// out[b,t,c] = (1/(t+1)) * sum_{j<=t} x[b,j,c]  (cumulative mean along T).
// The weights input is mathematically redundant and is never read.

#define BATCH   16
#define SEQ_T   8192
#define CH      64
#define C4      (CH / 4)          // 16 float4 lanes per row
#define TILE_T  512               // rows per tile
#define NTILES  (SEQ_T / TILE_T)  // 16 tiles per batch
#define ROWS_PT 16                // rows per thread in scan kernel
#define CHUNKS  (TILE_T / ROWS_PT)// 32 chunks per tile

// Scratch: per-(batch, tile) channel sums. 16*16*64 floats = 64 KB.
__device__ float g_tile_sums[BATCH * NTILES * CH];

// ---------------------------------------------------------------------------
// Kernel 1: per-tile channel sums.
// Grid: BATCH*NTILES CTAs, 256 threads. Thread: c4 = tid%16, rowgroup = tid/16.
// ---------------------------------------------------------------------------
__global__ void __launch_bounds__(256) k_tile_sums(const float* __restrict__ x) {
    const int blk  = blockIdx.x;
    const int b    = blk / NTILES;
    const int tile = blk % NTILES;
    const int tid  = threadIdx.x;
    const int c4   = tid & 15;
    const int rg   = tid >> 4;    // 0..15

    const float4* xp = reinterpret_cast<const float4*>(x)
                     + ((size_t)(b * SEQ_T + tile * TILE_T + rg)) * C4 + c4;

    float4 acc = make_float4(0.f, 0.f, 0.f, 0.f);
    #pragma unroll 8
    for (int i = 0; i < TILE_T / 16; ++i) {
        float4 v = xp[(size_t)i * 16 * C4];
        acc.x += v.x; acc.y += v.y; acc.z += v.z; acc.w += v.w;
    }

    __shared__ float4 s[16][C4];
    s[rg][c4] = acc;
    __syncthreads();

    if (rg == 0) {
        float4 t = s[0][c4];
        #pragma unroll
        for (int i = 1; i < 16; ++i) {
            float4 v = s[i][c4];
            t.x += v.x; t.y += v.y; t.z += v.z; t.w += v.w;
        }
        reinterpret_cast<float4*>(g_tile_sums)[(size_t)(b * NTILES + tile) * C4 + c4] = t;
    }
}

// ---------------------------------------------------------------------------
// Kernel 2: full scan + scale + write.
// Grid: BATCH*NTILES CTAs, 512 threads. Thread: c4 = tid%16 (4 channels),
// chunk = tid/16 (16 consecutive rows held in registers).
// ---------------------------------------------------------------------------
__global__ void __launch_bounds__(512) k_scan(const float* __restrict__ x,
                                              float* __restrict__ out) {
    const int blk   = blockIdx.x;
    const int b     = blk / NTILES;
    const int tile  = blk % NTILES;
    const int tid   = threadIdx.x;
    const int c4    = tid & 15;
    const int chunk = tid >> 4;   // 0..31
    const int row0  = tile * TILE_T + chunk * ROWS_PT;   // first global row

    const float4* xp = reinterpret_cast<const float4*>(x)
                     + ((size_t)b * SEQ_T + row0) * C4 + c4;

    // Load 16 rows x 4 channels into registers (independent loads -> high MLP).
    float4 v[ROWS_PT];
    #pragma unroll
    for (int r = 0; r < ROWS_PT; ++r) v[r] = xp[(size_t)r * C4];

    // In-register inclusive scan over the 16 rows.
    #pragma unroll
    for (int r = 1; r < ROWS_PT; ++r) {
        v[r].x += v[r - 1].x; v[r].y += v[r - 1].y;
        v[r].z += v[r - 1].z; v[r].w += v[r - 1].w;
    }

    // Publish chunk totals. Layout [chunk][c4] -> LDS.128 conflict-free.
    __shared__ float4 s[CHUNKS][C4];
    s[chunk][c4] = v[ROWS_PT - 1];
    __syncthreads();

    // Base = sum of all previous tiles' channel sums (tiny array, L2-broadcast).
    float4 base = make_float4(0.f, 0.f, 0.f, 0.f);
    const float4* ts = reinterpret_cast<const float4*>(g_tile_sums)
                     + (size_t)b * NTILES * C4 + c4;
    for (int t = 0; t < tile; ++t) {
        float4 w = ts[(size_t)t * C4];
        base.x += w.x; base.y += w.y; base.z += w.z; base.w += w.w;
    }

    // + exclusive prefix of earlier chunks within this tile.
    for (int j = 0; j < chunk; ++j) {
        float4 w = s[j][c4];
        base.x += w.x; base.y += w.y; base.z += w.z; base.w += w.w;
    }

    // Scale by 1/(t+1) and write (float4-coalesced).
    float4* op = reinterpret_cast<float4*>(out)
               + ((size_t)b * SEQ_T + row0) * C4 + c4;
    #pragma unroll
    for (int r = 0; r < ROWS_PT; ++r) {
        const float inv = 1.0f / (float)(row0 + r + 1);
        float4 o;
        o.x = (v[r].x + base.x) * inv;
        o.y = (v[r].y + base.y) * inv;
        o.z = (v[r].z + base.z) * inv;
        o.w = (v[r].w + base.w) * inv;
        op[(size_t)r * C4] = o;
    }
}

// ---------------------------------------------------------------------------
// Launch: identify x by element count (weights is 8192*8192, never read).
// Graph-capturable: two plain kernel launches, no sync, no alloc.
// ---------------------------------------------------------------------------
extern "C" void kernel_launch(void* const* d_in, const int* in_sizes, int n_in,
                              void* d_out, int out_size) {
    const long long x_elems = (long long)BATCH * SEQ_T * CH;
    const float* x = (const float*)d_in[0];
    for (int i = 0; i < n_in; ++i) {
        if ((long long)in_sizes[i] == x_elems) { x = (const float*)d_in[i]; break; }
    }
    float* out = (float*)d_out;

    k_tile_sums<<<BATCH * NTILES, 256>>>(x);
    k_scan<<<BATCH * NTILES, 512>>>(x, out);
}

// round 5
// speedup vs baseline: 1.0683x; 1.0683x over previous
#include <cuda_runtime.h>

// out[b,t,c] = (1/(t+1)) * sum_{j<=t} x[b,j,c]  — cumulative mean along T.
// Single-pass tiled scan with decoupled per-tile aggregate publication.
// The weights input (8192x8192 softmax'd causal mask) is mathematically
// redundant and is never read.

#define BATCH   16
#define SEQ_T   8192
#define CH      64
#define C4      16                 // float4 lanes per row
#define TILE_T  256                // rows per tile
#define NTILES  32                 // tiles per batch (SEQ_T / TILE_T)
#define ROWS_PT 8                  // rows per thread
#define CHUNKS  32                 // TILE_T / ROWS_PT
#define NBLK    (BATCH * NTILES)   // 512 CTAs

// Scratch: per-(batch,tile) channel aggregates + completion flags.
__device__ float g_sums[NBLK * CH];     // 128 KB
__device__ int   g_flags[NBLK];         // 2 KB, zeroed via memsetAsync each launch

__global__ void __launch_bounds__(512, 2)
k_fused(const float* __restrict__ x, float* __restrict__ out) {
    const int blk   = blockIdx.x;
    const int b     = blk >> 5;            // NTILES == 32
    const int tile  = blk & (NTILES - 1);
    const int tid   = threadIdx.x;
    const int c4    = tid & 15;
    const int chunk = tid >> 4;            // 0..31
    const int tile_row0 = tile * TILE_T;
    const int row0      = tile_row0 + chunk * ROWS_PT;

    __shared__ float4 s[CHUNKS][C4];       // chunk totals
    __shared__ float4 s_base[C4];          // prefix from earlier tiles
    __shared__ float  s_inv[TILE_T];       // 1/(t+1) for this tile's rows

    // Precompute reciprocals once per tile (256 MUFUs/CTA instead of 4096).
    if (tid < TILE_T) {
        s_inv[tid] = 1.0f / (float)(tile_row0 + tid + 1);
    }

    // ---- Load 8 rows x 4 channels, in-register inclusive scan ----
    const float4* xp = reinterpret_cast<const float4*>(x)
                     + ((size_t)b * SEQ_T + row0) * C4 + c4;
    float4 v[ROWS_PT];
    #pragma unroll
    for (int r = 0; r < ROWS_PT; ++r) v[r] = __ldcs(xp + (size_t)r * C4);
    #pragma unroll
    for (int r = 1; r < ROWS_PT; ++r) {
        v[r].x += v[r-1].x; v[r].y += v[r-1].y;
        v[r].z += v[r-1].z; v[r].w += v[r-1].w;
    }
    s[chunk][c4] = v[ROWS_PT - 1];
    __syncthreads();

    // ---- Warp 0: publish tile aggregate, then gather predecessor aggregates ----
    if (tid < 32) {
        if (tid < 16) {
            float4 agg = s[0][tid];
            #pragma unroll
            for (int j = 1; j < CHUNKS; ++j) {
                float4 w = s[j][tid];
                agg.x += w.x; agg.y += w.y; agg.z += w.z; agg.w += w.w;
            }
            reinterpret_cast<float4*>(g_sums)[blk * C4 + tid] = agg;
            __threadfence();
            atomicAdd(&g_flags[blk], 1);   // reader waits for ==16
        }
        // Poll: lane l waits on predecessor tile l of this batch.
        if (tid < tile) {
            volatile int* f = g_flags + ((b << 5) + tid);
            while (*f != 16) { }
        }
        __syncwarp();
        __threadfence();
        if (tid < 16) {
            float4 base = make_float4(0.f, 0.f, 0.f, 0.f);
            const float4* gs = reinterpret_cast<const float4*>(g_sums)
                             + (size_t)(b << 5) * C4 + tid;
            for (int t = 0; t < tile; ++t) {   // independent L2 loads, pipelined
                float4 w = gs[t * C4];
                base.x += w.x; base.y += w.y; base.z += w.z; base.w += w.w;
            }
            s_base[tid] = base;
        }
    }
    __syncthreads();

    // ---- Per-thread: base + exclusive prefix of earlier chunks ----
    float4 p = s_base[c4];
    for (int j = 0; j < chunk; ++j) {
        float4 w = s[j][c4];
        p.x += w.x; p.y += w.y; p.z += w.z; p.w += w.w;
    }

    // Reciprocals for this thread's 8 rows (two broadcast float4 smem reads).
    const float4* iv = reinterpret_cast<const float4*>(s_inv) + chunk * 2;
    const float4 i0 = iv[0], i1 = iv[1];
    const float invs[ROWS_PT] = { i0.x, i0.y, i0.z, i0.w, i1.x, i1.y, i1.z, i1.w };

    float4* op = reinterpret_cast<float4*>(out)
               + ((size_t)b * SEQ_T + row0) * C4 + c4;
    #pragma unroll
    for (int r = 0; r < ROWS_PT; ++r) {
        const float inv = invs[r];
        float4 o;
        o.x = (v[r].x + p.x) * inv;
        o.y = (v[r].y + p.y) * inv;
        o.z = (v[r].z + p.z) * inv;
        o.w = (v[r].w + p.w) * inv;
        __stcs(op + (size_t)r * C4, o);
    }
}

// ---------------------------------------------------------------------------
// Launch: zero flags (graph-capturable memsetAsync), identify x by element
// count (weights is 8192*8192 and never read), one fused kernel.
// ---------------------------------------------------------------------------
extern "C" void kernel_launch(void* const* d_in, const int* in_sizes, int n_in,
                              void* d_out, int out_size) {
    const long long x_elems = (long long)BATCH * SEQ_T * CH;
    const float* x = (const float*)d_in[0];
    for (int i = 0; i < n_in; ++i) {
        if ((long long)in_sizes[i] == x_elems) { x = (const float*)d_in[i]; break; }
    }
    float* out = (float*)d_out;

    void* flags_ptr = nullptr;
    cudaGetSymbolAddress(&flags_ptr, g_flags);
    cudaMemsetAsync(flags_ptr, 0, NBLK * sizeof(int), 0);

    k_fused<<<NBLK, 512>>>(x, out);
}

// round 9
// speedup vs baseline: 1.3093x; 1.2257x over previous
#include <cuda_runtime.h>

// out[b,t,c] = (1/(t+1)) * sum_{j<=t} x[b,j,c]  — cumulative mean along T.
// One-wave single-pass scan: 256 CTAs (all resident), each owning a 512-row
// tile. Phase A sums the tile (keeps it L2-hot), decoupled publish/poll of
// tile aggregates, Phase B re-reads the tile from L2 and streams the scaled
// running sum to out. The 8192x8192 weights input is mathematically
// redundant (softmax of causal zeros -> row t = 1/(t+1) ones) and is never read.

#define BATCH   16
#define SEQ_T   8192
#define CH      64
#define C4      16                 // float4 lanes per row
#define TILE_T  512                // rows per tile
#define NTILES  16                 // tiles per batch
#define CHUNKS  32                 // chunks per tile (512 threads / 16 c4)
#define ROWS_PT 16                 // rows per thread
#define NBLK    (BATCH * NTILES)   // 256 CTAs -> one wave at 2 CTAs/SM

__device__ float g_sums[NBLK * CH];     // per-(batch,tile) channel aggregates
__device__ int   g_flags[NBLK];         // zeroed via memsetAsync each launch

__global__ void __launch_bounds__(512, 2)
k_onewave(const float* __restrict__ x, float* __restrict__ out) {
    const int blk   = blockIdx.x;
    const int b     = blk >> 4;            // NTILES == 16
    const int tile  = blk & (NTILES - 1);
    const int tid   = threadIdx.x;
    const int c4    = tid & 15;
    const int chunk = tid >> 4;            // 0..31
    const int tile_row0 = tile * TILE_T;
    const int row0      = tile_row0 + chunk * ROWS_PT;

    __shared__ float4 s[CHUNKS][C4];       // chunk sums
    __shared__ float4 s_base[C4];          // prefix from earlier tiles
    __shared__ float  s_inv[TILE_T];       // 1/(t+1) for this tile's rows

    s_inv[tid] = 1.0f / (float)(tile_row0 + tid + 1);

    // ---- Phase A: sum 16 rows x 4 channels (cached loads keep tile in L2) ----
    const float4* xp = reinterpret_cast<const float4*>(x)
                     + ((size_t)b * SEQ_T + row0) * C4 + c4;
    float4 acc = make_float4(0.f, 0.f, 0.f, 0.f);
    #pragma unroll
    for (int r = 0; r < ROWS_PT; ++r) {
        float4 v = xp[(size_t)r * C4];     // default caching: stays L2-resident
        acc.x += v.x; acc.y += v.y; acc.z += v.z; acc.w += v.w;
    }
    s[chunk][c4] = acc;
    __syncthreads();

    // ---- Warp 0: publish tile aggregate, poll predecessors, gather base ----
    if (tid < 32) {
        if (tid < 16) {
            float4 agg = s[0][tid];
            #pragma unroll
            for (int j = 1; j < CHUNKS; ++j) {
                float4 w = s[j][tid];
                agg.x += w.x; agg.y += w.y; agg.z += w.z; agg.w += w.w;
            }
            reinterpret_cast<float4*>(g_sums)[blk * C4 + tid] = agg;
            __threadfence();
            atomicAdd(&g_flags[blk], 1);   // readers wait for ==16
        }
        if (tid < tile) {                  // lane l polls predecessor tile l
            volatile int* f = g_flags + ((b << 4) + tid);
            while (*f != 16) { }
        }
        __syncwarp();
        __threadfence();
        if (tid < 16) {
            float4 base = make_float4(0.f, 0.f, 0.f, 0.f);
            const float4* gs = reinterpret_cast<const float4*>(g_sums)
                             + (size_t)(b << 4) * C4 + tid;
            for (int t = 0; t < tile; ++t) {
                float4 w = gs[t * C4];
                base.x += w.x; base.y += w.y; base.z += w.z; base.w += w.w;
            }
            s_base[tid] = base;
        }
    }
    __syncthreads();

    // ---- Running start = base + exclusive prefix of earlier chunks ----
    float4 run = s_base[c4];
    for (int j = 0; j < chunk; ++j) {
        float4 w = s[j][c4];
        run.x += w.x; run.y += w.y; run.z += w.z; run.w += w.w;
    }

    // ---- Phase B: re-read tile (L2-hot), stream scaled running sum out ----
    float4* op = reinterpret_cast<float4*>(out)
               + ((size_t)b * SEQ_T + row0) * C4 + c4;
    const float* iv = s_inv + chunk * ROWS_PT;
    #pragma unroll 4
    for (int r = 0; r < ROWS_PT; ++r) {
        float4 v = __ldcs(xp + (size_t)r * C4);   // L2 hit; no further reuse
        run.x += v.x; run.y += v.y; run.z += v.z; run.w += v.w;
        const float inv = iv[r];
        float4 o;
        o.x = run.x * inv; o.y = run.y * inv;
        o.z = run.z * inv; o.w = run.w * inv;
        __stcs(op + (size_t)r * C4, o);
    }
}

// ---------------------------------------------------------------------------
// Launch: zero flags (graph-capturable memsetAsync), identify x by element
// count (weights is 8192*8192 and never read), one fused kernel.
// ---------------------------------------------------------------------------
extern "C" void kernel_launch(void* const* d_in, const int* in_sizes, int n_in,
                              void* d_out, int out_size) {
    const long long x_elems = (long long)BATCH * SEQ_T * CH;
    const float* x = (const float*)d_in[0];
    for (int i = 0; i < n_in; ++i) {
        if ((long long)in_sizes[i] == x_elems) { x = (const float*)d_in[i]; break; }
    }
    float* out = (float*)d_out;

    void* flags_ptr = nullptr;
    cudaGetSymbolAddress(&flags_ptr, g_flags);
    cudaMemsetAsync(flags_ptr, 0, NBLK * sizeof(int), 0);

    k_onewave<<<NBLK, 512>>>(x, out);
}